// round 14
// baseline (speedup 1.0000x reference)
#include <cuda_runtime.h>

// Problem constants
#define NB      4
#define NDET    128
#define NT      2048
#define NPIX    65536            // 256*256
#define DC      4                // dets per chunk (SMEM = DC*NT*16B = 128KB)
#define NCHUNK  32               // NDET / DC
#define NCP     16               // chunk pairs
#define NPPAIR  32768            // pixel pairs (NPIX/2)
#define THREADS 1024
#define W2      (NCP * NPPAIR)   // 524,288 (chunk-pair, pixel-pair) units
#define WPB2    3584             // units per block (3.5 groups of 1024)
#define NBLK    ((W2 + WPB2 - 1) / WPB2)   // 147 blocks -> 1 wave
#define MAXG    4                // max 1024-pair groups per segment

// Scratch (static __device__ — no allocations allowed)
__device__ uint4 g_lutP[NCHUNK * NPIX];   // 16 MB packed lut [chunk][pixel]

// ---------------------------------------------------------------------------
// Packed f32x2 helpers (Blackwell dual-FMA).
// ---------------------------------------------------------------------------
__device__ __forceinline__ unsigned long long pk2(float lo, float hi) {
    unsigned long long r;
    asm("mov.b64 %0, {%1, %2};" : "=l"(r) : "f"(lo), "f"(hi));
    return r;
}
__device__ __forceinline__ void upk2(unsigned long long v, float& lo, float& hi) {
    asm("mov.b64 {%0, %1}, %2;" : "=f"(lo), "=f"(hi) : "l"(v));
}
__device__ __forceinline__ unsigned long long fma2(unsigned long long a,
                                                   unsigned long long b,
                                                   unsigned long long c) {
    unsigned long long d;
    asm("fma.rn.f32x2 %0, %1, %2, %3;" : "=l"(d) : "l"(a), "l"(b), "l"(c));
    return d;
}

// Pack (k_floor, alpha): bits[0:11)=k0 clamped, bit11=valid, bits[12:32)=alpha q20.
__device__ __forceinline__ unsigned pack_lut(float kf, float a) {
    int k = (int)kf;
    unsigned valid = ((unsigned)k < 2047u) ? (1u << 11) : 0u;   // 0 <= k < NT-1
    int k0 = min(max(k, 0), NT - 2);
    unsigned aq = (unsigned)(a * 1048576.0f);
    if (aq > 1048575u) aq = 1048575u;
    return (unsigned)k0 | valid | (aq << 12);
}

// ---------------------------------------------------------------------------
// Kernel 1: pack + transpose lut [pixel][64 f4] -> [chunk][pixel] uint4.
// Unchanged (measured ~14-15.5us, near 80MB DRAM floor). Also zeroes d_out.
// ---------------------------------------------------------------------------
__global__ void __launch_bounds__(512)
lut_pack_kernel(const float4* __restrict__ lut4, float4* __restrict__ outz) {
    __shared__ uint2 tile[64][65];          // [px_local][f]  ~33 KB, padded
    const int t = threadIdx.x;
    const size_t base = (size_t)blockIdx.x * 4096;   // 64 pixels x 64 f

    if (t < 64) outz[blockIdx.x * 64 + t] = make_float4(0.f, 0.f, 0.f, 0.f);

    #pragma unroll
    for (int i = 0; i < 8; i++) {
        int n = t + i * 512;
        float4 v = __ldg(lut4 + base + n);
        uint2 u;
        u.x = pack_lut(v.x, v.y);
        u.y = pack_lut(v.z, v.w);
        tile[n >> 6][n & 63] = u;
    }
    __syncthreads();

    const int c   = t >> 4;                 // chunk 0..31
    const int pl0 = t & 15;
    const size_t pbase = (size_t)blockIdx.x * 64;
    #pragma unroll
    for (int j = 0; j < 4; j++) {
        int pl = pl0 + j * 16;
        uint2 a = tile[pl][2 * c];
        uint2 b = tile[pl][2 * c + 1];
        g_lutP[(size_t)c * NPIX + pbase + pl] = make_uint4(a.x, a.y, b.x, b.y);
    }
}

// ---------------------------------------------------------------------------
// Accumulate one pixel's packed-lut entry against the staged chunk.
// ---------------------------------------------------------------------------
extern __shared__ float4 s_sino[];   // [DC][NT]  128 KB

__device__ __forceinline__ void accum_px(uint4 L, const float* apod,
                                         unsigned long long& acc_xy,
                                         unsigned long long& acc_zw) {
    unsigned u[DC] = {L.x, L.y, L.z, L.w};
    #pragma unroll
    for (int j = 0; j < DC; j++) {
        unsigned v = u[j];
        int   k0  = (int)(v & 0x7FFu);                  // 0..2046
        float wgt = (v & 0x800u) ? apod[j] : 0.0f;
        float a   = (float)(v >> 12) * (1.0f / 1048576.0f);

        float4 s0 = s_sino[j * NT + k0];
        float4 s1 = s_sino[j * NT + k0 + 1];

        float wa = wgt * a;
        float w0 = wgt - wa;

        unsigned long long w0p = pk2(w0, w0), wap = pk2(wa, wa);
        acc_xy = fma2(w0p, pk2(s0.x, s0.y), fma2(wap, pk2(s1.x, s1.y), acc_xy));
        acc_zw = fma2(w0p, pk2(s0.z, s0.w), fma2(wap, pk2(s1.z, s1.w), acc_zw));
    }
}

// ---------------------------------------------------------------------------
// Kernel 2: main backprojection — persistent balanced grid over
// (chunk-pair, pixel-pair) units. Each segment: stage chunk 2cp, accumulate
// its groups into registers, re-stage chunk 2cp+1 into the SAME tile,
// accumulate again, then flush with red.global.add.v2.f32 (one per batch
// per pixel-pair). Atomic instruction count /4 vs round 13.
// ---------------------------------------------------------------------------
__global__ void __launch_bounds__(THREADS, 1)
bp_main_kernel(const float* __restrict__ sino, float* __restrict__ out) {
    const int tid = threadIdx.x;

    int u    = blockIdx.x * WPB2;
    int uend = min(u + WPB2, W2);

    while (u < uend) {
        const int cp      = u >> 15;             // chunk pair
        const int pr0     = u & (NPPAIR - 1);    // first pixel pair in cp
        const int seg_end = min((cp + 1) << 15, uend);
        const int npairs  = seg_end - u;         // <= WPB2

        // acc[group][0..3]: pixel0 xy, pixel0 zw, pixel1 xy, pixel1 zw
        unsigned long long acc[MAXG][4];
        #pragma unroll
        for (int g = 0; g < MAXG; g++) {
            acc[g][0] = 0ull; acc[g][1] = 0ull; acc[g][2] = 0ull; acc[g][3] = 0ull;
        }

        #pragma unroll
        for (int h = 0; h < 2; h++) {
            const int c = 2 * cp + h;

            __syncthreads();   // protect SMEM from previous readers

            // Stage DC det rows of chunk c, transposing batches into float4.
            #pragma unroll 8
            for (int i = tid; i < DC * NT; i += THREADS) {
                int j = i >> 11;
                int k = i & (NT - 1);
                const float* sp = sino + (size_t)(c * DC + j) * NT + k;
                float4 v;
                v.x = __ldg(sp + 0 * NDET * NT);
                v.y = __ldg(sp + 1 * NDET * NT);
                v.z = __ldg(sp + 2 * NDET * NT);
                v.w = __ldg(sp + 3 * NDET * NT);
                s_sino[i] = v;
            }

            // Hann weights, pre-divided by the exact norm (sum apod = 63.5).
            float apod[DC];
            #pragma unroll
            for (int j = 0; j < DC; j++) {
                int d = c * DC + j;
                apod[j] = (0.5f - 0.5f *
                           cosf(6.2831853071795864769f * (float)d / 127.0f))
                          * (1.0f / 63.5f);
            }

            __syncthreads();

            const uint4* __restrict__ lp = g_lutP + (size_t)c * NPIX;

            #pragma unroll
            for (int g = 0; g < MAXG; g++) {
                const int pr = pr0 + g * THREADS + tid;
                if (g * THREADS + tid < npairs) {
                    const int p = 2 * pr;
                    uint4 L0 = __ldg(lp + p);
                    uint4 L1 = __ldg(lp + p + 1);
                    accum_px(L0, apod, acc[g][0], acc[g][1]);
                    accum_px(L1, apod, acc[g][2], acc[g][3]);
                }
            }
        }

        // Flush: one red.v2 per batch per pixel-pair.
        #pragma unroll
        for (int g = 0; g < MAXG; g++) {
            if (g * THREADS + tid < npairs) {
                const int p = 2 * (pr0 + g * THREADS + tid);
                float x0, y0, z0, w0, x1, y1, z1, w1;
                upk2(acc[g][0], x0, y0);
                upk2(acc[g][1], z0, w0);
                upk2(acc[g][2], x1, y1);
                upk2(acc[g][3], z1, w1);
                float* o0 = out + 0 * NPIX + p;
                float* o1 = out + 1 * NPIX + p;
                float* o2 = out + 2 * NPIX + p;
                float* o3 = out + 3 * NPIX + p;
                asm volatile("red.global.add.v2.f32 [%0], {%1, %2};"
                             :: "l"(o0), "f"(x0), "f"(x1) : "memory");
                asm volatile("red.global.add.v2.f32 [%0], {%1, %2};"
                             :: "l"(o1), "f"(y0), "f"(y1) : "memory");
                asm volatile("red.global.add.v2.f32 [%0], {%1, %2};"
                             :: "l"(o2), "f"(z0), "f"(z1) : "memory");
                asm volatile("red.global.add.v2.f32 [%0], {%1, %2};"
                             :: "l"(o3), "f"(w0), "f"(w1) : "memory");
            }
        }

        u = seg_end;
    }
}

// ---------------------------------------------------------------------------
extern "C" void kernel_launch(void* const* d_in, const int* in_sizes, int n_in,
                              void* d_out, int out_size) {
    const float*  sino = (const float*)d_in[0];
    const float4* lut4 = (const float4*)d_in[1];
    float*        out  = (float*)d_out;

    cudaFuncSetAttribute(bp_main_kernel,
                         cudaFuncAttributeMaxDynamicSharedMemorySize,
                         DC * NT * (int)sizeof(float4));

    lut_pack_kernel<<<1024, 512>>>(lut4, (float4*)out);

    bp_main_kernel<<<NBLK, THREADS, DC * NT * sizeof(float4)>>>(sino, out);
}

// round 15
// speedup vs baseline: 1.1327x; 1.1327x over previous
#include <cuda_runtime.h>

// Problem constants
#define NB      4
#define NDET    128
#define NT      2048
#define NPIX    65536            // 256*256
#define DC      4                // dets per chunk (SMEM = DC*NT*16B = 128KB)
#define NCHUNK  32               // NDET / DC
#define THREADS 1024
#define TOTALW  (NCHUNK * NPIX)  // 2,097,152 px-chunk work units
#define WPB     14336            // work per block (14 * 1024), 1024-aligned
#define NBLK    ((TOTALW + WPB - 1) / WPB)   // 147 blocks -> 1 wave on 148 SMs

// Scratch (static __device__ — no allocations allowed)
__device__ uint4 g_lutP[NCHUNK * NPIX];   // 16 MB packed lut [chunk][pixel]

// ---------------------------------------------------------------------------
// Packed f32x2 helpers (Blackwell dual-FMA).
// ---------------------------------------------------------------------------
__device__ __forceinline__ unsigned long long pk2(float lo, float hi) {
    unsigned long long r;
    asm("mov.b64 %0, {%1, %2};" : "=l"(r) : "f"(lo), "f"(hi));
    return r;
}
__device__ __forceinline__ void upk2(unsigned long long v, float& lo, float& hi) {
    asm("mov.b64 {%0, %1}, %2;" : "=f"(lo), "=f"(hi) : "l"(v));
}
__device__ __forceinline__ unsigned long long fma2(unsigned long long a,
                                                   unsigned long long b,
                                                   unsigned long long c) {
    unsigned long long d;
    asm("fma.rn.f32x2 %0, %1, %2, %3;" : "=l"(d) : "l"(a), "l"(b), "l"(c));
    return d;
}
__device__ __forceinline__ unsigned long long add2(unsigned long long a,
                                                   unsigned long long b) {
    unsigned long long d;
    asm("add.rn.f32x2 %0, %1, %2;" : "=l"(d) : "l"(a), "l"(b));
    return d;
}

// Pack (k_floor, alpha): bits[0:11)=k0 clamped, bit11=valid, bits[12:32)=alpha q20.
__device__ __forceinline__ unsigned pack_lut(float kf, float a) {
    int k = (int)kf;
    unsigned valid = ((unsigned)k < 2047u) ? (1u << 11) : 0u;   // 0 <= k < NT-1
    int k0 = min(max(k, 0), NT - 2);
    unsigned aq = (unsigned)(a * 1048576.0f);
    if (aq > 1048575u) aq = 1048575u;
    return (unsigned)k0 | valid | (aq << 12);
}

// ---------------------------------------------------------------------------
// Kernel 1: pack + transpose lut [pixel][64 f4] -> [chunk][pixel] uint4.
// Unchanged (measured ~14us, near its 80MB DRAM floor). Also zeroes d_out.
// ---------------------------------------------------------------------------
__global__ void __launch_bounds__(512)
lut_pack_kernel(const float4* __restrict__ lut4, float4* __restrict__ outz) {
    __shared__ uint2 tile[64][65];          // [px_local][f]  ~33 KB, padded
    const int t = threadIdx.x;
    const size_t base = (size_t)blockIdx.x * 4096;   // 64 pixels x 64 f

    if (t < 64) outz[blockIdx.x * 64 + t] = make_float4(0.f, 0.f, 0.f, 0.f);

    #pragma unroll
    for (int i = 0; i < 8; i++) {
        int n = t + i * 512;
        float4 v = __ldg(lut4 + base + n);
        uint2 u;
        u.x = pack_lut(v.x, v.y);
        u.y = pack_lut(v.z, v.w);
        tile[n >> 6][n & 63] = u;
    }
    __syncthreads();

    const int c   = t >> 4;                 // chunk 0..31
    const int pl0 = t & 15;
    const size_t pbase = (size_t)blockIdx.x * 64;
    #pragma unroll
    for (int j = 0; j < 4; j++) {
        int pl = pl0 + j * 16;
        uint2 a = tile[pl][2 * c];
        uint2 b = tile[pl][2 * c + 1];
        g_lutP[(size_t)c * NPIX + pbase + pl] = make_uint4(a.x, a.y, b.x, b.y);
    }
}

// ---------------------------------------------------------------------------
// Per-pixel accumulate against the staged chunk, with SPLIT chains:
// dets {0,1} -> chain A, dets {2,3} -> chain B (half the dependent depth).
// ---------------------------------------------------------------------------
extern __shared__ float4 s_sino[];   // [DC][NT]  128 KB

__device__ __forceinline__ void accum_px(uint4 L, const float* apod,
                                         float& ax, float& ay,
                                         float& az, float& aw) {
    unsigned u[DC] = {L.x, L.y, L.z, L.w};

    unsigned long long xyA = 0ull, zwA = 0ull;   // dets 0,1
    unsigned long long xyB = 0ull, zwB = 0ull;   // dets 2,3

    #pragma unroll
    for (int j = 0; j < DC; j++) {
        unsigned v = u[j];
        int   k0  = (int)(v & 0x7FFu);                  // 0..2046
        float wgt = (v & 0x800u) ? apod[j] : 0.0f;
        float a   = (float)(v >> 12) * (1.0f / 1048576.0f);

        float4 s0 = s_sino[j * NT + k0];
        float4 s1 = s_sino[j * NT + k0 + 1];

        float wa = wgt * a;
        float w0 = wgt - wa;

        unsigned long long w0p = pk2(w0, w0), wap = pk2(wa, wa);
        if (j < 2) {
            xyA = fma2(w0p, pk2(s0.x, s0.y), fma2(wap, pk2(s1.x, s1.y), xyA));
            zwA = fma2(w0p, pk2(s0.z, s0.w), fma2(wap, pk2(s1.z, s1.w), zwA));
        } else {
            xyB = fma2(w0p, pk2(s0.x, s0.y), fma2(wap, pk2(s1.x, s1.y), xyB));
            zwB = fma2(w0p, pk2(s0.z, s0.w), fma2(wap, pk2(s1.z, s1.w), zwB));
        }
    }

    upk2(add2(xyA, xyB), ax, ay);
    upk2(add2(zwA, zwB), az, aw);
}

// ---------------------------------------------------------------------------
// Kernel 2: main backprojection — persistent balanced grid (round-13
// structure) with the group loop manually unrolled x2: two independent
// pixels per iteration = 16 independent LDS.128 + 2 lut LDG for the
// scheduler to interleave. Coalesced no-return float atomics into out.
// ---------------------------------------------------------------------------
__global__ void __launch_bounds__(THREADS, 1)
bp_main_kernel(const float* __restrict__ sino, float* __restrict__ out) {
    const int tid = threadIdx.x;

    int w    = blockIdx.x * WPB;
    int wend = min(w + WPB, TOTALW);

    while (w < wend) {
        const int c   = w >> 16;            // w / NPIX
        const int px0 = w & (NPIX - 1);     // w % NPIX
        const int seg_end = min((c + 1) << 16, wend);
        const int ngroups = (seg_end - w) >> 10;   // px count / 1024

        __syncthreads();   // protect SMEM from previous segment's readers

        // Stage DC det rows of chunk c, transposing batches into float4.
        #pragma unroll 8
        for (int i = tid; i < DC * NT; i += THREADS) {
            int j = i >> 11;            // det within chunk
            int k = i & (NT - 1);
            const float* sp = sino + (size_t)(c * DC + j) * NT + k;
            float4 v;
            v.x = __ldg(sp + 0 * NDET * NT);
            v.y = __ldg(sp + 1 * NDET * NT);
            v.z = __ldg(sp + 2 * NDET * NT);
            v.w = __ldg(sp + 3 * NDET * NT);
            s_sino[i] = v;
        }

        // Hann weights, pre-divided by the exact norm (sum apod = 63.5).
        float apod[DC];
        #pragma unroll
        for (int j = 0; j < DC; j++) {
            int d = c * DC + j;
            apod[j] = (0.5f - 0.5f * cosf(6.2831853071795864769f * (float)d / 127.0f))
                      * (1.0f / 63.5f);
        }

        __syncthreads();

        const uint4* __restrict__ lp = g_lutP + (size_t)c * NPIX + px0 + tid;

        int g = 0;
        // x2-unrolled body: two independent pixels in flight.
        for (; g + 2 <= ngroups; g += 2) {
            uint4 L0 = __ldg(lp + g * THREADS);
            uint4 L1 = __ldg(lp + (g + 1) * THREADS);

            float ax0, ay0, az0, aw0, ax1, ay1, az1, aw1;
            accum_px(L0, apod, ax0, ay0, az0, aw0);
            accum_px(L1, apod, ax1, ay1, az1, aw1);

            const int p0 = px0 + g * THREADS + tid;
            const int p1 = p0 + THREADS;
            atomicAdd(out + 0 * NPIX + p0, ax0);
            atomicAdd(out + 1 * NPIX + p0, ay0);
            atomicAdd(out + 2 * NPIX + p0, az0);
            atomicAdd(out + 3 * NPIX + p0, aw0);
            atomicAdd(out + 0 * NPIX + p1, ax1);
            atomicAdd(out + 1 * NPIX + p1, ay1);
            atomicAdd(out + 2 * NPIX + p1, az1);
            atomicAdd(out + 3 * NPIX + p1, aw1);
        }
        // Remainder group.
        if (g < ngroups) {
            uint4 L0 = __ldg(lp + g * THREADS);
            float ax0, ay0, az0, aw0;
            accum_px(L0, apod, ax0, ay0, az0, aw0);
            const int p0 = px0 + g * THREADS + tid;
            atomicAdd(out + 0 * NPIX + p0, ax0);
            atomicAdd(out + 1 * NPIX + p0, ay0);
            atomicAdd(out + 2 * NPIX + p0, az0);
            atomicAdd(out + 3 * NPIX + p0, aw0);
        }

        w = seg_end;
    }
}

// ---------------------------------------------------------------------------
extern "C" void kernel_launch(void* const* d_in, const int* in_sizes, int n_in,
                              void* d_out, int out_size) {
    const float*  sino = (const float*)d_in[0];
    const float4* lut4 = (const float4*)d_in[1];
    float*        out  = (float*)d_out;

    cudaFuncSetAttribute(bp_main_kernel,
                         cudaFuncAttributeMaxDynamicSharedMemorySize,
                         DC * NT * (int)sizeof(float4));

    lut_pack_kernel<<<1024, 512>>>(lut4, (float4*)out);

    bp_main_kernel<<<NBLK, THREADS, DC * NT * sizeof(float4)>>>(sino, out);
}

// round 17
// speedup vs baseline: 1.3887x; 1.2260x over previous
#include <cuda_runtime.h>
#include <cuda_fp16.h>

// Problem constants
#define NB      4
#define NDET    128
#define NT      2048
#define NPIX    65536            // 256*256
#define DC      4                // dets per chunk (tile = DC*NT*8B = 64KB)
#define NCHUNK  32               // NDET / DC
#define THREADS 512
#define TOTALW  (NCHUNK * NPIX)  // 2,097,152 px-chunk work units
#define WPB     7168             // work per block (14 * 512), 512-aligned
#define NBLK    ((TOTALW + WPB - 1) / WPB)   // 293 blocks -> 1 wave @ 2/SM

// Scratch (static __device__ — no allocations allowed)
__device__ uint4 g_lutP[NCHUNK * NPIX];   // 16 MB packed lut [chunk][pixel]

// ---------------------------------------------------------------------------
// Packed f32x2 helpers (Blackwell dual-FMA).
// ---------------------------------------------------------------------------
__device__ __forceinline__ unsigned long long pk2(float lo, float hi) {
    unsigned long long r;
    asm("mov.b64 %0, {%1, %2};" : "=l"(r) : "f"(lo), "f"(hi));
    return r;
}
__device__ __forceinline__ void upk2(unsigned long long v, float& lo, float& hi) {
    asm("mov.b64 {%0, %1}, %2;" : "=f"(lo), "=f"(hi) : "l"(v));
}
__device__ __forceinline__ unsigned long long fma2(unsigned long long a,
                                                   unsigned long long b,
                                                   unsigned long long c) {
    unsigned long long d;
    asm("fma.rn.f32x2 %0, %1, %2, %3;" : "=l"(d) : "l"(a), "l"(b), "l"(c));
    return d;
}

// Pack (k_floor, alpha): bits[0:11)=k0 clamped, bit11=valid, bits[16:32)=alpha fp16.
__device__ __forceinline__ unsigned pack_lut(float kf, float a) {
    int k = (int)kf;
    unsigned valid = ((unsigned)k < 2047u) ? (1u << 11) : 0u;   // 0 <= k < NT-1
    int k0 = min(max(k, 0), NT - 2);
    unsigned ah = (unsigned)__half_as_ushort(__float2half_rn(a));
    return (unsigned)k0 | valid | (ah << 16);
}

// ---------------------------------------------------------------------------
// Kernel 1: pack + transpose lut [pixel][64 f4] -> [chunk][pixel] uint4.
// Structure unchanged (near its 80MB DRAM floor). Also zeroes d_out.
// ---------------------------------------------------------------------------
__global__ void __launch_bounds__(512)
lut_pack_kernel(const float4* __restrict__ lut4, float4* __restrict__ outz) {
    __shared__ uint2 tile[64][65];          // [px_local][f]  ~33 KB, padded
    const int t = threadIdx.x;
    const size_t base = (size_t)blockIdx.x * 4096;   // 64 pixels x 64 f

    if (t < 64) outz[blockIdx.x * 64 + t] = make_float4(0.f, 0.f, 0.f, 0.f);

    #pragma unroll
    for (int i = 0; i < 8; i++) {
        int n = t + i * 512;
        float4 v = __ldg(lut4 + base + n);
        uint2 u;
        u.x = pack_lut(v.x, v.y);
        u.y = pack_lut(v.z, v.w);
        tile[n >> 6][n & 63] = u;
    }
    __syncthreads();

    const int c   = t >> 4;                 // chunk 0..31
    const int pl0 = t & 15;
    const size_t pbase = (size_t)blockIdx.x * 64;
    #pragma unroll
    for (int j = 0; j < 4; j++) {
        int pl = pl0 + j * 16;
        uint2 a = tile[pl][2 * c];
        uint2 b = tile[pl][2 * c + 1];
        g_lutP[(size_t)c * NPIX + pbase + pl] = make_uint4(a.x, a.y, b.x, b.y);
    }
}

// ---------------------------------------------------------------------------
// Kernel 2: main backprojection — persistent balanced grid, fp16 sino tile.
// 293 blocks x 512 threads, 2 blocks/SM (64 KB tile each): one block's
// staging overlaps the other's compute. Per segment: stage chunk c as
// half4-over-batches (uint2 per k), then per pixel: packed-lut prefetch,
// per det 2x LDS.64 (s0,s1), fp16 lerp (HMUL2/HFMA2), cvt to f32, FFMA2
// apod-weighted accumulate, coalesced no-return float atomics into out.
// ---------------------------------------------------------------------------
extern __shared__ uint2 s_sino[];   // [DC][NT] half4 entries, 64 KB

__global__ void __launch_bounds__(THREADS, 2)
bp_main_kernel(const float* __restrict__ sino, float* __restrict__ out) {
    const int tid = threadIdx.x;
    const __half2 ones2 = __float2half2_rn(1.0f);

    int w    = blockIdx.x * WPB;
    int wend = min(w + WPB, TOTALW);

    while (w < wend) {
        const int c   = w >> 16;            // w / NPIX
        const int px0 = w & (NPIX - 1);     // w % NPIX
        const int seg_end = min((c + 1) << 16, wend);
        const int ngroups = (seg_end - w) / THREADS;

        __syncthreads();   // protect SMEM from previous segment's readers

        // Stage DC det rows of chunk c: 4 batch floats -> half4 (uint2).
        #pragma unroll 4
        for (int i = tid; i < DC * NT; i += THREADS) {
            int j = i >> 11;            // det within chunk
            int k = i & (NT - 1);
            const float* sp = sino + (size_t)(c * DC + j) * NT + k;
            float b0 = __ldg(sp + 0 * NDET * NT);
            float b1 = __ldg(sp + 1 * NDET * NT);
            float b2 = __ldg(sp + 2 * NDET * NT);
            float b3 = __ldg(sp + 3 * NDET * NT);
            __half2 h01 = __floats2half2_rn(b0, b1);
            __half2 h23 = __floats2half2_rn(b2, b3);
            uint2 e;
            e.x = *reinterpret_cast<unsigned*>(&h01);
            e.y = *reinterpret_cast<unsigned*>(&h23);
            s_sino[i] = e;
        }

        // Hann weights, pre-divided by the exact norm (sum apod = 63.5).
        float apod[DC];
        #pragma unroll
        for (int j = 0; j < DC; j++) {
            int d = c * DC + j;
            apod[j] = (0.5f - 0.5f * cosf(6.2831853071795864769f * (float)d / 127.0f))
                      * (1.0f / 63.5f);
        }

        __syncthreads();

        const uint4* __restrict__ lp = g_lutP + (size_t)c * NPIX + px0 + tid;

        // Software-pipelined group loop (lut is L2-resident after pack).
        uint4 L = __ldg(lp);
        for (int g = 0; g < ngroups; g++) {
            uint4 N = L;
            if (g + 1 < ngroups) N = __ldg(lp + (g + 1) * THREADS);

            unsigned u[DC] = {L.x, L.y, L.z, L.w};

            unsigned long long acc_xy = 0ull, acc_zw = 0ull;

            #pragma unroll
            for (int j = 0; j < DC; j++) {
                unsigned v = u[j];
                int   k0  = (int)(v & 0x7FFu);                  // 0..2046
                float wgt = (v & 0x800u) ? apod[j] : 0.0f;

                __half2 a2 = __half2half2(__ushort_as_half((unsigned short)(v >> 16)));
                __half2 m2 = __hsub2(ones2, a2);                // 1 - alpha

                uint2 q0 = s_sino[j * NT + k0];
                uint2 q1 = s_sino[j * NT + k0 + 1];
                __half2 s001 = *reinterpret_cast<__half2*>(&q0.x);
                __half2 s023 = *reinterpret_cast<__half2*>(&q0.y);
                __half2 s101 = *reinterpret_cast<__half2*>(&q1.x);
                __half2 s123 = *reinterpret_cast<__half2*>(&q1.y);

                __half2 r01 = __hfma2(a2, s101, __hmul2(m2, s001));
                __half2 r23 = __hfma2(a2, s123, __hmul2(m2, s023));

                float2 f01 = __half22float2(r01);
                float2 f23 = __half22float2(r23);

                unsigned long long wp = pk2(wgt, wgt);
                acc_xy = fma2(wp, pk2(f01.x, f01.y), acc_xy);
                acc_zw = fma2(wp, pk2(f23.x, f23.y), acc_zw);
            }

            float ax, ay, az, aw;
            upk2(acc_xy, ax, ay);
            upk2(acc_zw, az, aw);

            const int p = px0 + g * THREADS + tid;
            atomicAdd(out + 0 * NPIX + p, ax);
            atomicAdd(out + 1 * NPIX + p, ay);
            atomicAdd(out + 2 * NPIX + p, az);
            atomicAdd(out + 3 * NPIX + p, aw);

            L = N;
        }

        w = seg_end;
    }
}

// ---------------------------------------------------------------------------
extern "C" void kernel_launch(void* const* d_in, const int* in_sizes, int n_in,
                              void* d_out, int out_size) {
    const float*  sino = (const float*)d_in[0];
    const float4* lut4 = (const float4*)d_in[1];
    float*        out  = (float*)d_out;

    cudaFuncSetAttribute(bp_main_kernel,
                         cudaFuncAttributeMaxDynamicSharedMemorySize,
                         DC * NT * (int)sizeof(uint2));

    lut_pack_kernel<<<1024, 512>>>(lut4, (float4*)out);

    bp_main_kernel<<<NBLK, THREADS, DC * NT * sizeof(uint2)>>>(sino, out);
}